// round 1
// baseline (speedup 1.0000x reference)
#include <cuda_runtime.h>
#include <math.h>

// Problem constants
#define NB   8
#define SS   512          // S == T == HD
#define DD   4096
#define HH   8
#define HD_  512
#define MT   (NB*SS)      // 4096 rows for the big GEMMs
#define BSTR ((size_t)SS*SS)   // 262144, per-(n,h) matrix stride

// Scratch (device globals: allocation-guard safe). 5 x 64MB.
__device__ float g_q [NB*SS*DD];
__device__ float g_k [NB*SS*DD];
__device__ float g_v [NB*SS*DD];
__device__ float g_s [NB*HH*SS*SS];
__device__ float g_y2[NB*SS*DD];

// ---------------------------------------------------------------------------
// NT GEMM: C[m,n] = scale * sum_k A[m,k]*B[n,k]  (+ bias[n])
// A: row-major MxK, B: row-major NxK (i.e. torch Linear weight), C: MxN.
// 128x128 tile, BK=8, 256 threads, 8x8 per thread. blockIdx.z = batch.
// ---------------------------------------------------------------------------
__global__ __launch_bounds__(256, 2)
void gemm_nt(const float* __restrict__ A, const float* __restrict__ B,
             float* __restrict__ C, const float* __restrict__ bias,
             int M, int Nn, int K,
             long long sA, long long sB, long long sC, float scale)
{
    const int bz = blockIdx.z;
    A += (size_t)bz * sA;
    B += (size_t)bz * sB;
    C += (size_t)bz * sC;

    __shared__ float As[8][128];
    __shared__ float Bs[8][128];

    const int tid = threadIdx.x;
    const int m0 = blockIdx.y * 128;
    const int n0 = blockIdx.x * 128;

    // load indices: one float4 per thread per tile
    const int lr = tid >> 1;          // 0..127 row within tile
    const int lc = (tid & 1) * 4;     // k offset 0 or 4

    const int tx = tid & 15;          // 0..15 -> 8 output cols each
    const int ty = tid >> 4;          // 0..15 -> 8 output rows each

    float acc[8][8];
    #pragma unroll
    for (int i = 0; i < 8; i++)
        #pragma unroll
        for (int j = 0; j < 8; j++) acc[i][j] = 0.f;

    const float* Aptr = A + (size_t)(m0 + lr) * K + lc;
    const float* Bptr = B + (size_t)(n0 + lr) * K + lc;

    for (int kk = 0; kk < K; kk += 8) {
        float4 av = *(const float4*)(Aptr + kk);
        float4 bv = *(const float4*)(Bptr + kk);
        As[lc + 0][lr] = av.x; As[lc + 1][lr] = av.y;
        As[lc + 2][lr] = av.z; As[lc + 3][lr] = av.w;
        Bs[lc + 0][lr] = bv.x; Bs[lc + 1][lr] = bv.y;
        Bs[lc + 2][lr] = bv.z; Bs[lc + 3][lr] = bv.w;
        __syncthreads();

        #pragma unroll
        for (int k = 0; k < 8; k++) {
            float4 a0 = *(const float4*)&As[k][ty * 8];
            float4 a1 = *(const float4*)&As[k][ty * 8 + 4];
            float4 b0 = *(const float4*)&Bs[k][tx * 8];
            float4 b1 = *(const float4*)&Bs[k][tx * 8 + 4];
            float ar[8] = {a0.x,a0.y,a0.z,a0.w,a1.x,a1.y,a1.z,a1.w};
            float br[8] = {b0.x,b0.y,b0.z,b0.w,b1.x,b1.y,b1.z,b1.w};
            #pragma unroll
            for (int i = 0; i < 8; i++)
                #pragma unroll
                for (int j = 0; j < 8; j++)
                    acc[i][j] += ar[i] * br[j];
        }
        __syncthreads();
    }

    // epilogue
    float bb[8];
    #pragma unroll
    for (int j = 0; j < 8; j++)
        bb[j] = bias ? bias[n0 + tx * 8 + j] : 0.f;

    #pragma unroll
    for (int i = 0; i < 8; i++) {
        float* Crow = C + (size_t)(m0 + ty * 8 + i) * Nn + n0 + tx * 8;
        float4 c0, c1;
        c0.x = acc[i][0] * scale + bb[0];
        c0.y = acc[i][1] * scale + bb[1];
        c0.z = acc[i][2] * scale + bb[2];
        c0.w = acc[i][3] * scale + bb[3];
        c1.x = acc[i][4] * scale + bb[4];
        c1.y = acc[i][5] * scale + bb[5];
        c1.z = acc[i][6] * scale + bb[6];
        c1.w = acc[i][7] * scale + bb[7];
        *(float4*)(Crow)     = c0;
        *(float4*)(Crow + 4) = c1;
    }
}

// ---------------------------------------------------------------------------
// Fused: softmax over S axis (per column t), elementwise * v, and scatter into
// the (0,2,1,3)-transposed layout Y2[n, a, h*512 + b] for the final GEMM.
// One block per (n,h) pair, 512 threads = one per column t. Fully coalesced.
// ---------------------------------------------------------------------------
__global__ __launch_bounds__(512)
void softmax_mul_scatter(const float* __restrict__ S, const float* __restrict__ V,
                         float* __restrict__ Y2)
{
    const int b = blockIdx.x;          // n*H + h  (64)
    const int n = b / HH, h = b % HH;
    const int c = threadIdx.x;         // column t (== hd index b)

    const float* Sp = S + (size_t)b * BSTR;
    const float* Vp = V + (size_t)b * BSTR;

    // pass 1: online max + sum over s (coalesced across c)
    float mx = -INFINITY, sum = 0.f;
    for (int s = 0; s < SS; s++) {
        float v  = Sp[(size_t)s * SS + c];
        float m2 = fmaxf(mx, v);
        sum = sum * __expf(mx - m2) + __expf(v - m2);
        mx  = m2;
    }
    const float inv = 1.f / sum;

    // pass 2: normalize, multiply by v, scatter transposed
    float* Yp = Y2 + (size_t)n * SS * DD + (size_t)h * HD_ + c;
    for (int s = 0; s < SS; s++) {
        float a = __expf(Sp[(size_t)s * SS + c] - mx) * inv;
        Yp[(size_t)s * DD] = a * Vp[(size_t)s * SS + c];
    }
}

// ---------------------------------------------------------------------------
extern "C" void kernel_launch(void* const* d_in, const int* in_sizes, int n_in,
                              void* d_out, int out_size)
{
    const float* query = (const float*)d_in[0];
    const float* key   = (const float*)d_in[1];
    const float* value = (const float*)d_in[2];
    const float* Wq    = (const float*)d_in[3];
    const float* bq    = (const float*)d_in[4];
    const float* Wk    = (const float*)d_in[5];
    const float* bk    = (const float*)d_in[6];
    const float* Wv    = (const float*)d_in[7];
    const float* bv    = (const float*)d_in[8];
    const float* Wo    = (const float*)d_in[9];
    const float* bo    = (const float*)d_in[10];
    float* out = (float*)d_out;

    float *q, *k, *v, *s, *y2;
    cudaGetSymbolAddress((void**)&q,  g_q);
    cudaGetSymbolAddress((void**)&k,  g_k);
    cudaGetSymbolAddress((void**)&v,  g_v);
    cudaGetSymbolAddress((void**)&s,  g_s);
    cudaGetSymbolAddress((void**)&y2, g_y2);

    const dim3 gp(DD / 128, MT / 128, 1);      // 32x32 blocks, big GEMMs
    const dim3 gs(SS / 128, SS / 128, NB * HH);// 4x4x64, scores

    // Projections: X @ W^T + b
    gemm_nt<<<gp, 256>>>(query, Wq, q, bq, MT, DD, DD, 0, 0, 0, 1.f);
    gemm_nt<<<gp, 256>>>(key,   Wk, k, bk, MT, DD, DD, 0, 0, 0, 1.f);
    gemm_nt<<<gp, 256>>>(value, Wv, v, bv, MT, DD, DD, 0, 0, 0, 1.f);

    // Scores: 64 batched (512,512,512) NT GEMMs, scaled by 1/sqrt(512)
    gemm_nt<<<gs, 256>>>(q, k, s, nullptr, SS, SS, SS,
                         (long long)BSTR, (long long)BSTR, (long long)BSTR,
                         0.04419417382415922f);

    // Softmax(axis=S) * v, scattered into transposed layout
    softmax_mul_scatter<<<NB * HH, 512>>>(s, v, y2);

    // Output projection
    gemm_nt<<<gp, 256>>>(y2, Wo, out, bo, MT, DD, DD, 0, 0, 0, 1.f);
}

// round 3
// speedup vs baseline: 2.7609x; 2.7609x over previous
#include <cuda_runtime.h>
#include <cuda_bf16.h>
#include <math.h>
#include <stdint.h>

// Problem constants
#define NB   8
#define SS   512
#define DD   4096
#define HH   8
#define HD_  512
#define MT   (NB*SS)            // 4096
#define BSTR ((long long)SS*SS) // 262144
#define NELT (MT*DD)            // 16,777,216

// ---------------- scratch (device globals; allocation-guard safe) -----------
__device__ float g_v [NELT];            // V projection (fp32)
__device__ float g_s [NB*HH*SS*SS];     // scores (fp32)
__device__ __nv_bfloat16 g_xh[NELT], g_xl[NELT];   // activation split
__device__ __nv_bfloat16 g_wh[NELT], g_wl[NELT];   // weight split
__device__ __nv_bfloat16 g_qh[NELT], g_ql[NELT];   // Q split / later Y2 split
__device__ __nv_bfloat16 g_kh[NELT], g_kl[NELT];   // K split

// ---------------- PTX helpers (all compute_103-baseline legal) --------------
__device__ __forceinline__ uint32_t smem_u32(const void* p) {
    uint32_t a;
    asm("{ .reg .u64 t; cvta.to.shared.u64 t, %1; cvt.u32.u64 %0, t; }"
        : "=r"(a) : "l"(p));
    return a;
}
__device__ __forceinline__ void cp16(uint32_t s, const void* g) {
    asm volatile("cp.async.cg.shared.global [%0], [%1], 16;" :: "r"(s), "l"(g));
}
__device__ __forceinline__ void cp_commit() {
    asm volatile("cp.async.commit_group;");
}
template <int N> __device__ __forceinline__ void cp_wait() {
    asm volatile("cp.async.wait_group %0;" :: "n"(N));
}
__device__ __forceinline__ void ldsm4(uint32_t& r0, uint32_t& r1,
                                      uint32_t& r2, uint32_t& r3, uint32_t a) {
    asm volatile("ldmatrix.sync.aligned.m8n8.x4.shared.b16 {%0,%1,%2,%3}, [%4];"
                 : "=r"(r0), "=r"(r1), "=r"(r2), "=r"(r3) : "r"(a));
}
__device__ __forceinline__ void mma16816(float* d, const uint32_t* a,
                                         uint32_t b0, uint32_t b1) {
    asm volatile(
        "mma.sync.aligned.m16n8k16.row.col.f32.bf16.bf16.f32 "
        "{%0,%1,%2,%3}, {%4,%5,%6,%7}, {%8,%9}, {%0,%1,%2,%3};"
        : "+f"(d[0]), "+f"(d[1]), "+f"(d[2]), "+f"(d[3])
        : "r"(a[0]), "r"(a[1]), "r"(a[2]), "r"(a[3]), "r"(b0), "r"(b1));
}

// ---------------- tile constants --------------------------------------------
#define BM 128
#define BN 256
#define BK 64
// smem stage layout (bytes): 128B rows, SW128 swizzle
#define ST_A_HI 0
#define ST_A_LO 16384
#define ST_B_HI 32768
#define ST_B_LO 65536
#define ST_SIZE 98304
#define SMEM_TOTAL (2*ST_SIZE)   // 196,608

// ---------------------------------------------------------------------------
// HMMA NT GEMM, bf16 hi/lo split 3-pass: C = scale*(Ah+Al)(Bh+Bl)^T (+bias)
// A: MxK row-major (M = BM*gridDim.y), B: NxK row-major. blockIdx.z = batch.
// Outputs: fp32 C and/or bf16 split Ch/Cl.
// ---------------------------------------------------------------------------
__global__ void __launch_bounds__(256, 1)
gemm_tc(const __nv_bfloat16* __restrict__ Ah, const __nv_bfloat16* __restrict__ Al,
        const __nv_bfloat16* __restrict__ Bh, const __nv_bfloat16* __restrict__ Bl,
        float* __restrict__ C, __nv_bfloat16* __restrict__ Ch,
        __nv_bfloat16* __restrict__ Cl, const float* __restrict__ bias,
        int Nn, int Kk, long long sA, long long sB, long long sC, float scale)
{
    extern __shared__ __align__(1024) char smem[];
    const uint32_t sb = smem_u32(smem);
    const int tid = threadIdx.x;
    const int bz = blockIdx.z;
    Ah += (long long)bz * sA;  Al += (long long)bz * sA;
    Bh += (long long)bz * sB;  Bl += (long long)bz * sB;

    const int m0 = blockIdx.y * BM;
    const int n0 = blockIdx.x * BN;
    const int nst = Kk / BK;

    // ---- stage loader: 16B chunks, SW128 swizzle -------------------------
    auto load_stage = [&](int s, int buf) {
        const uint32_t stg = sb + buf * ST_SIZE;
        const int kk = s * BK;
        #pragma unroll
        for (int it = 0; it < 4; it++) {          // A: 128 rows x 8 chunks
            int idx = tid + it * 256;
            int r = idx >> 3, c = idx & 7;
            long long go = (long long)(m0 + r) * Kk + kk + c * 8;
            uint32_t sw = (uint32_t)(r * 128 + ((c * 16) ^ ((r & 7) << 4)));
            cp16(stg + ST_A_HI + sw, Ah + go);
            cp16(stg + ST_A_LO + sw, Al + go);
        }
        #pragma unroll
        for (int it = 0; it < 8; it++) {          // B: 256 rows x 8 chunks
            int idx = tid + it * 256;
            int r = idx >> 3, c = idx & 7;
            long long go = (long long)(n0 + r) * Kk + kk + c * 8;
            uint32_t sw = (uint32_t)(r * 128 + ((c * 16) ^ ((r & 7) << 4)));
            cp16(stg + ST_B_HI + sw, Bh + go);
            cp16(stg + ST_B_LO + sw, Bl + go);
        }
    };

    // ---- warp layout: 2x4 warps, warp tile 64x64 -------------------------
    const int wid = tid >> 5, lane = tid & 31;
    const int warp_m = wid & 1;        // 0..1
    const int warp_n = wid >> 1;       // 0..3
    const int arow0 = warp_m * 64 + (lane & 15);
    const int brow0 = warp_n * 64 + (lane & 15);
    const uint32_t halfsel = (uint32_t)((lane >> 4) * 16);

    float acc[4][8][4];
    #pragma unroll
    for (int i = 0; i < 4; i++)
        #pragma unroll
        for (int j = 0; j < 8; j++)
            #pragma unroll
            for (int k = 0; k < 4; k++) acc[i][j][k] = 0.f;

    load_stage(0, 0); cp_commit();
    if (nst > 1) { load_stage(1, 1); cp_commit(); }

    for (int c = 0; c < nst; c++) {
        if (c + 2 < nst) cp_wait<1>(); else cp_wait<0>();
        __syncthreads();
        const uint32_t stg = sb + (c & 1) * ST_SIZE;

        #pragma unroll
        for (int ks = 0; ks < 4; ks++) {
            const uint32_t ko = (uint32_t)(ks * 32);
            uint32_t ah[4][4], al[4][4];
            #pragma unroll
            for (int mt = 0; mt < 4; mt++) {
                int row = arow0 + mt * 16;
                uint32_t ad = stg + ST_A_HI + (uint32_t)row * 128
                            + ((ko + halfsel) ^ (uint32_t)((row & 7) << 4));
                ldsm4(ah[mt][0], ah[mt][1], ah[mt][2], ah[mt][3], ad);
                ldsm4(al[mt][0], al[mt][1], al[mt][2], al[mt][3],
                      ad + (ST_A_LO - ST_A_HI));
            }
            #pragma unroll
            for (int g = 0; g < 4; g++) {
                int row = brow0 + g * 16;
                uint32_t bd = stg + ST_B_HI + (uint32_t)row * 128
                            + ((ko + halfsel) ^ (uint32_t)((row & 7) << 4));
                uint32_t bh[4], bl[4];
                ldsm4(bh[0], bh[1], bh[2], bh[3], bd);
                ldsm4(bl[0], bl[1], bl[2], bl[3], bd + (ST_B_LO - ST_B_HI));
                #pragma unroll
                for (int half = 0; half < 2; half++) {
                    const int nt = g * 2 + half;
                    const uint32_t b0h = bh[half], b1h = bh[half + 2];
                    const uint32_t b0l = bl[half], b1l = bl[half + 2];
                    #pragma unroll
                    for (int mt = 0; mt < 4; mt++) {
                        mma16816(acc[mt][nt], ah[mt], b0h, b1h);
                        mma16816(acc[mt][nt], ah[mt], b0l, b1l);
                        mma16816(acc[mt][nt], al[mt], b0h, b1h);
                    }
                }
            }
        }
        __syncthreads();
        if (c + 2 < nst) { load_stage(c + 2, c & 1); cp_commit(); }
    }

    // ---- epilogue --------------------------------------------------------
    const int r0 = lane >> 2;
    const int c0 = (lane & 3) * 2;
    float* Cp = C ? (C + (long long)bz * sC) : nullptr;
    __nv_bfloat16* Chp = Ch ? (Ch + (long long)bz * sC) : nullptr;
    __nv_bfloat16* Clp = Cl ? (Cl + (long long)bz * sC) : nullptr;

    #pragma unroll
    for (int mt = 0; mt < 4; mt++) {
        #pragma unroll
        for (int nt = 0; nt < 8; nt++) {
            const int gc = n0 + warp_n * 64 + nt * 8 + c0;
            float b0 = 0.f, b1 = 0.f;
            if (bias) { b0 = __ldg(&bias[gc]); b1 = __ldg(&bias[gc + 1]); }
            #pragma unroll
            for (int hh = 0; hh < 2; hh++) {
                const int gr = m0 + warp_m * 64 + mt * 16 + r0 + hh * 8;
                float v0 = acc[mt][nt][hh * 2 + 0] * scale + b0;
                float v1 = acc[mt][nt][hh * 2 + 1] * scale + b1;
                if (Cp) {
                    float2 o = make_float2(v0, v1);
                    *(float2*)(Cp + (long long)gr * Nn + gc) = o;
                }
                if (Chp) {
                    __nv_bfloat16 h0 = __float2bfloat16(v0);
                    __nv_bfloat16 h1 = __float2bfloat16(v1);
                    __nv_bfloat16 l0 = __float2bfloat16(v0 - __bfloat162float(h0));
                    __nv_bfloat16 l1 = __float2bfloat16(v1 - __bfloat162float(h1));
                    __nv_bfloat162 hp(h0, h1), lp(l0, l1);
                    *(uint32_t*)(Chp + (long long)gr * Nn + gc) = *(uint32_t*)&hp;
                    *(uint32_t*)(Clp + (long long)gr * Nn + gc) = *(uint32_t*)&lp;
                }
            }
        }
    }
}

// ---------------------------------------------------------------------------
// fp32 -> bf16 hi/lo split
// ---------------------------------------------------------------------------
__global__ void __launch_bounds__(256)
split_bf16(const float4* __restrict__ in, uint2* __restrict__ hi,
           uint2* __restrict__ lo, int n4)
{
    int i = blockIdx.x * blockDim.x + threadIdx.x;
    if (i >= n4) return;
    float4 a = in[i];
    __nv_bfloat16 h0 = __float2bfloat16(a.x), h1 = __float2bfloat16(a.y);
    __nv_bfloat16 h2 = __float2bfloat16(a.z), h3 = __float2bfloat16(a.w);
    __nv_bfloat16 l0 = __float2bfloat16(a.x - __bfloat162float(h0));
    __nv_bfloat16 l1 = __float2bfloat16(a.y - __bfloat162float(h1));
    __nv_bfloat16 l2 = __float2bfloat16(a.z - __bfloat162float(h2));
    __nv_bfloat16 l3 = __float2bfloat16(a.w - __bfloat162float(h3));
    __nv_bfloat162 hA(h0, h1), hB(h2, h3), lA(l0, l1), lB(l2, l3);
    hi[i] = make_uint2(*(uint32_t*)&hA, *(uint32_t*)&hB);
    lo[i] = make_uint2(*(uint32_t*)&lA, *(uint32_t*)&lB);
}

// ---------------------------------------------------------------------------
// softmax over S axis * v, scattered transposed, emitted as bf16 hi/lo split
// ---------------------------------------------------------------------------
__global__ void __launch_bounds__(512)
softmax_mul_scatter(const float* __restrict__ S, const float* __restrict__ V,
                    __nv_bfloat16* __restrict__ Yh, __nv_bfloat16* __restrict__ Yl)
{
    const int b = blockIdx.x;
    const int n = b / HH, h = b % HH;
    const int c = threadIdx.x;

    const float* Sp = S + (long long)b * BSTR;
    const float* Vp = V + (long long)b * BSTR;

    float mx = -INFINITY, sum = 0.f;
    for (int s = 0; s < SS; s++) {
        float v  = Sp[(long long)s * SS + c];
        float m2 = fmaxf(mx, v);
        sum = sum * __expf(mx - m2) + __expf(v - m2);
        mx  = m2;
    }
    const float inv = 1.f / sum;

    __nv_bfloat16* Yhp = Yh + (long long)n * SS * DD + (long long)h * HD_ + c;
    __nv_bfloat16* Ylp = Yl + (long long)n * SS * DD + (long long)h * HD_ + c;
    for (int s = 0; s < SS; s++) {
        float a = __expf(Sp[(long long)s * SS + c] - mx) * inv;
        float y = a * Vp[(long long)s * SS + c];
        __nv_bfloat16 hh = __float2bfloat16(y);
        __nv_bfloat16 ll = __float2bfloat16(y - __bfloat162float(hh));
        Yhp[(long long)s * DD] = hh;
        Ylp[(long long)s * DD] = ll;
    }
}

// ---------------------------------------------------------------------------
extern "C" void kernel_launch(void* const* d_in, const int* in_sizes, int n_in,
                              void* d_out, int out_size)
{
    const float* query = (const float*)d_in[0];
    const float* key   = (const float*)d_in[1];
    const float* value = (const float*)d_in[2];
    const float* Wq    = (const float*)d_in[3];
    const float* bq    = (const float*)d_in[4];
    const float* Wk    = (const float*)d_in[5];
    const float* bk    = (const float*)d_in[6];
    const float* Wv    = (const float*)d_in[7];
    const float* bv    = (const float*)d_in[8];
    const float* Wo    = (const float*)d_in[9];
    const float* bo    = (const float*)d_in[10];
    float* out = (float*)d_out;

    float *v, *s;
    __nv_bfloat16 *xh, *xl, *wh, *wl, *qh, *ql, *kh, *kl;
    cudaGetSymbolAddress((void**)&v,  g_v);
    cudaGetSymbolAddress((void**)&s,  g_s);
    cudaGetSymbolAddress((void**)&xh, g_xh);  cudaGetSymbolAddress((void**)&xl, g_xl);
    cudaGetSymbolAddress((void**)&wh, g_wh);  cudaGetSymbolAddress((void**)&wl, g_wl);
    cudaGetSymbolAddress((void**)&qh, g_qh);  cudaGetSymbolAddress((void**)&ql, g_ql);
    cudaGetSymbolAddress((void**)&kh, g_kh);  cudaGetSymbolAddress((void**)&kl, g_kl);

    cudaFuncSetAttribute(gemm_tc, cudaFuncAttributeMaxDynamicSharedMemorySize, SMEM_TOTAL);

    const int n4 = NELT / 4;
    const int sg = (n4 + 255) / 256;
    const dim3 gp(DD / BN, MT / BM, 1);        // 16 x 32 CTAs, projections
    const dim3 gs(SS / BN, SS / BM, NB * HH);  // 2 x 4 x 64, scores

    // Q projection -> split bf16
    split_bf16<<<sg, 256>>>((const float4*)query, (uint2*)xh, (uint2*)xl, n4);
    split_bf16<<<sg, 256>>>((const float4*)Wq,    (uint2*)wh, (uint2*)wl, n4);
    gemm_tc<<<gp, 256, SMEM_TOTAL>>>(xh, xl, wh, wl, nullptr, qh, ql, bq,
                                     DD, DD, 0, 0, 0, 1.f);
    // K projection -> split bf16
    split_bf16<<<sg, 256>>>((const float4*)key, (uint2*)xh, (uint2*)xl, n4);
    split_bf16<<<sg, 256>>>((const float4*)Wk,  (uint2*)wh, (uint2*)wl, n4);
    gemm_tc<<<gp, 256, SMEM_TOTAL>>>(xh, xl, wh, wl, nullptr, kh, kl, bk,
                                     DD, DD, 0, 0, 0, 1.f);
    // V projection -> fp32
    split_bf16<<<sg, 256>>>((const float4*)value, (uint2*)xh, (uint2*)xl, n4);
    split_bf16<<<sg, 256>>>((const float4*)Wv,    (uint2*)wh, (uint2*)wl, n4);
    gemm_tc<<<gp, 256, SMEM_TOTAL>>>(xh, xl, wh, wl, v, nullptr, nullptr, bv,
                                     DD, DD, 0, 0, 0, 1.f);
    // Scores: 64 batched (512,512,512), scaled by 1/sqrt(512)
    gemm_tc<<<gs, 256, SMEM_TOTAL>>>(qh, ql, kh, kl, s, nullptr, nullptr, nullptr,
                                     SS, SS, BSTR, BSTR, BSTR,
                                     0.04419417382415922f);
    // Softmax * v -> transposed, split bf16 (reuse qh/ql as Y2 split)
    softmax_mul_scatter<<<NB * HH, 512>>>(s, v, qh, ql);
    // Output projection -> fp32 out
    split_bf16<<<sg, 256>>>((const float4*)Wo, (uint2*)wh, (uint2*)wl, n4);
    gemm_tc<<<gp, 256, SMEM_TOTAL>>>(qh, ql, wh, wl, out, nullptr, nullptr, bo,
                                     DD, DD, 0, 0, 0, 1.f);
}

// round 4
// speedup vs baseline: 3.2263x; 1.1685x over previous
#include <cuda_runtime.h>
#include <cuda_bf16.h>
#include <cuda_fp16.h>
#include <math.h>
#include <stdint.h>

// Problem constants
#define NB   8
#define SS   512
#define DD   4096
#define HH   8
#define HD_  512
#define MT   (NB*SS)            // 4096
#define BSTR ((long long)SS*SS) // 262144
#define NELT (MT*DD)            // 16,777,216

// ---------------- scratch (device globals; allocation-guard safe) -----------
__device__ float g_v[NELT];             // V projection (fp32)
__device__ float g_s[NELT];             // scores (fp32)
// bf16 3-pass path (Q/K projections + scores)
__device__ __nv_bfloat16 g_qa_h[NELT], g_qa_l[NELT];   // query act split
__device__ __nv_bfloat16 g_ka_h[NELT], g_ka_l[NELT];   // key act split
__device__ __nv_bfloat16 g_wq_h[NELT], g_wq_l[NELT];
__device__ __nv_bfloat16 g_wk_h[NELT], g_wk_l[NELT];
__device__ __nv_bfloat16 g_q_h [NELT], g_q_l [NELT];   // Q proj out split
__device__ __nv_bfloat16 g_k_h [NELT], g_k_l [NELT];   // K proj out split
// fp16 reduced-pass path (V proj 1-pass, O proj 2-pass)
__device__ __half g_va[NELT];                           // value act fp16
__device__ __half g_wv[NELT];                           // Wv fp16
__device__ __half g_wo[NELT];                           // Wo fp16
__device__ __half g_y_h[NELT], g_y_l[NELT];             // Y2 fp16 hi/lo

// ---------------- PTX helpers (compute_103-baseline legal) ------------------
__device__ __forceinline__ uint32_t smem_u32(const void* p) {
    uint32_t a;
    asm("{ .reg .u64 t; cvta.to.shared.u64 t, %1; cvt.u32.u64 %0, t; }"
        : "=r"(a) : "l"(p));
    return a;
}
__device__ __forceinline__ void cp16(uint32_t s, const void* g) {
    asm volatile("cp.async.cg.shared.global [%0], [%1], 16;" :: "r"(s), "l"(g));
}
__device__ __forceinline__ void cp_commit() {
    asm volatile("cp.async.commit_group;");
}
template <int N> __device__ __forceinline__ void cp_wait() {
    asm volatile("cp.async.wait_group %0;" :: "n"(N));
}
__device__ __forceinline__ void ldsm4(uint32_t& r0, uint32_t& r1,
                                      uint32_t& r2, uint32_t& r3, uint32_t a) {
    asm volatile("ldmatrix.sync.aligned.m8n8.x4.shared.b16 {%0,%1,%2,%3}, [%4];"
                 : "=r"(r0), "=r"(r1), "=r"(r2), "=r"(r3) : "r"(a));
}
template<bool FP16>
__device__ __forceinline__ void mma16816(float* d, const uint32_t* a,
                                         uint32_t b0, uint32_t b1) {
    if constexpr (FP16) {
        asm volatile(
            "mma.sync.aligned.m16n8k16.row.col.f32.f16.f16.f32 "
            "{%0,%1,%2,%3}, {%4,%5,%6,%7}, {%8,%9}, {%0,%1,%2,%3};"
            : "+f"(d[0]), "+f"(d[1]), "+f"(d[2]), "+f"(d[3])
            : "r"(a[0]), "r"(a[1]), "r"(a[2]), "r"(a[3]), "r"(b0), "r"(b1));
    } else {
        asm volatile(
            "mma.sync.aligned.m16n8k16.row.col.f32.bf16.bf16.f32 "
            "{%0,%1,%2,%3}, {%4,%5,%6,%7}, {%8,%9}, {%0,%1,%2,%3};"
            : "+f"(d[0]), "+f"(d[1]), "+f"(d[2]), "+f"(d[3])
            : "r"(a[0]), "r"(a[1]), "r"(a[2]), "r"(a[3]), "r"(b0), "r"(b1));
    }
}

// ---------------- tile constants --------------------------------------------
#define BM 128
#define BN 256
#define BK 32
// Packed-row layout: two 64-row (A) / 128-row (B) groups share each 128B
// SW128 row: logical row r, k-chunk c16 -> phys = r & (G-1), half = r >> lgG,
// byte = phys*128 + ((half*64 + c16*16) ^ ((phys&7)<<4)).

// ---------------------------------------------------------------------------
// HMMA NT GEMM: C = scale * A B^T (+ bias).  Passes: AhBh [+ AhBl][+ AlBh].
// A: MxK row-major, B: NxK row-major. blockIdx.z = batch.
// ---------------------------------------------------------------------------
template<bool HAS_AL, bool HAS_BL, bool FP16>
__global__ void __launch_bounds__(256, 1)
gemm_tc(const uint16_t* __restrict__ Ah, const uint16_t* __restrict__ Al,
        const uint16_t* __restrict__ Bh, const uint16_t* __restrict__ Bl,
        float* __restrict__ C, __nv_bfloat16* __restrict__ Ch,
        __nv_bfloat16* __restrict__ Cl, const float* __restrict__ bias,
        int Nn, int Kk, long long sA, long long sB, long long sC, float scale)
{
    constexpr uint32_t SZ_A = 64 * 128;     // 8KB  (128 rows x 32k bf16, packed)
    constexpr uint32_t SZ_B = 128 * 128;    // 16KB (256 rows x 32k)
    constexpr uint32_t OFF_AH = 0;
    constexpr uint32_t OFF_AL = SZ_A;                    // if HAS_AL
    constexpr uint32_t OFF_BH = SZ_A * (1 + (HAS_AL ? 1 : 0));
    constexpr uint32_t STG_SZ = SZ_A * (1 + (HAS_AL ? 1 : 0))
                              + SZ_B * (1 + (HAS_BL ? 1 : 0));
    constexpr int STAGES = (192 * 1024 / STG_SZ) < 6 ? (192 * 1024 / STG_SZ) : 6;

    extern __shared__ __align__(1024) char smem[];
    const uint32_t sb = smem_u32(smem);
    const int tid = threadIdx.x;
    const int bz = blockIdx.z;
    Ah += (long long)bz * sA;  if (HAS_AL) Al += (long long)bz * sA;
    Bh += (long long)bz * sB;  if (HAS_BL) Bl += (long long)bz * sB;

    const int m0 = blockIdx.y * BM;
    const int n0 = blockIdx.x * BN;
    const int nst = Kk / BK;

    auto load_stage = [&](int s, int buf) {
        const uint32_t stg = sb + (uint32_t)buf * STG_SZ;
        const int kk = s * BK;
        #pragma unroll
        for (int it = 0; it < 2; it++) {          // A: 128 rows x 4 chunks
            int id = tid + it * 256;
            int r = id >> 2, c4 = id & 3;
            long long go = (long long)(m0 + r) * Kk + kk + c4 * 8;
            uint32_t ph = (uint32_t)(r & 63), hf = (uint32_t)(r >> 6);
            uint32_t so = ph * 128 + ((hf * 64 + c4 * 16) ^ ((ph & 7) << 4));
            cp16(stg + OFF_AH + so, Ah + go);
            if (HAS_AL) cp16(stg + OFF_AL + so, Al + go);
        }
        #pragma unroll
        for (int it = 0; it < 4; it++) {          // B: 256 rows x 4 chunks
            int id = tid + it * 256;
            int r = id >> 2, c4 = id & 3;
            long long go = (long long)(n0 + r) * Kk + kk + c4 * 8;
            uint32_t ph = (uint32_t)(r & 127), hf = (uint32_t)(r >> 7);
            uint32_t so = ph * 128 + ((hf * 64 + c4 * 16) ^ ((ph & 7) << 4));
            cp16(stg + OFF_BH + so, Bh + go);
            if (HAS_BL) cp16(stg + OFF_BH + SZ_B + so, Bl + go);
        }
    };

    // warp layout: 2x4 warps, warp tile 64x64
    const int wid = tid >> 5, lane = tid & 31;
    const int warp_m = wid & 1;
    const int warp_n = wid >> 1;
    const int arow0 = warp_m * 64 + (lane & 15);
    const int brow0 = warp_n * 64 + (lane & 15);
    const uint32_t halfsel = (uint32_t)((lane >> 4) * 16);

    float acc[4][8][4];
    #pragma unroll
    for (int i = 0; i < 4; i++)
        #pragma unroll
        for (int j = 0; j < 8; j++)
            #pragma unroll
            for (int k = 0; k < 4; k++) acc[i][j][k] = 0.f;

    #pragma unroll
    for (int s = 0; s < STAGES - 1; s++) {
        if (s < nst) { load_stage(s, s); cp_commit(); }
    }

    for (int c = 0; c < nst; c++) {
        cp_wait<STAGES - 2>();
        __syncthreads();
        if (c + STAGES - 1 < nst) {
            load_stage(c + STAGES - 1, (c + STAGES - 1) % STAGES);
            cp_commit();
        }
        const uint32_t stg = sb + (uint32_t)(c % STAGES) * STG_SZ;

        #pragma unroll
        for (int ks = 0; ks < 2; ks++) {
            uint32_t ah[4][4], al[4][4];
            #pragma unroll
            for (int mt = 0; mt < 4; mt++) {
                int row = arow0 + mt * 16;
                uint32_t ph = (uint32_t)(row & 63);
                uint32_t col = ((uint32_t)warp_m * 64 + (uint32_t)ks * 32 + halfsel)
                             ^ ((ph & 7) << 4);
                uint32_t ad = stg + OFF_AH + ph * 128 + col;
                ldsm4(ah[mt][0], ah[mt][1], ah[mt][2], ah[mt][3], ad);
                if (HAS_AL)
                    ldsm4(al[mt][0], al[mt][1], al[mt][2], al[mt][3], ad + SZ_A);
            }
            #pragma unroll
            for (int g = 0; g < 4; g++) {
                int row = brow0 + g * 16;
                uint32_t ph = (uint32_t)(row & 127);
                uint32_t hf = (uint32_t)(row >> 7);
                uint32_t col = (hf * 64 + (uint32_t)ks * 32 + halfsel)
                             ^ ((ph & 7) << 4);
                uint32_t bd = stg + OFF_BH + ph * 128 + col;
                uint32_t bh[4], bl[4];
                ldsm4(bh[0], bh[1], bh[2], bh[3], bd);
                if (HAS_BL) ldsm4(bl[0], bl[1], bl[2], bl[3], bd + SZ_B);
                #pragma unroll
                for (int half = 0; half < 2; half++) {
                    const int nt = g * 2 + half;
                    const uint32_t b0h = bh[half], b1h = bh[half + 2];
                    #pragma unroll
                    for (int mt = 0; mt < 4; mt++) {
                        mma16816<FP16>(acc[mt][nt], ah[mt], b0h, b1h);
                        if (HAS_BL)
                            mma16816<FP16>(acc[mt][nt], ah[mt], bl[half], bl[half + 2]);
                        if (HAS_AL)
                            mma16816<FP16>(acc[mt][nt], al[mt], b0h, b1h);
                    }
                }
            }
        }
    }

    // ---- epilogue --------------------------------------------------------
    const int r0 = lane >> 2;
    const int c0 = (lane & 3) * 2;
    float* Cp = C ? (C + (long long)bz * sC) : nullptr;
    __nv_bfloat16* Chp = Ch ? (Ch + (long long)bz * sC) : nullptr;
    __nv_bfloat16* Clp = Cl ? (Cl + (long long)bz * sC) : nullptr;

    #pragma unroll
    for (int mt = 0; mt < 4; mt++) {
        #pragma unroll
        for (int nt = 0; nt < 8; nt++) {
            const int gc = n0 + warp_n * 64 + nt * 8 + c0;
            float b0 = 0.f, b1 = 0.f;
            if (bias) { b0 = __ldg(&bias[gc]); b1 = __ldg(&bias[gc + 1]); }
            #pragma unroll
            for (int hh = 0; hh < 2; hh++) {
                const int gr = m0 + warp_m * 64 + mt * 16 + r0 + hh * 8;
                float v0 = acc[mt][nt][hh * 2 + 0] * scale + b0;
                float v1 = acc[mt][nt][hh * 2 + 1] * scale + b1;
                if (Cp) {
                    float2 o = make_float2(v0, v1);
                    *(float2*)(Cp + (long long)gr * Nn + gc) = o;
                }
                if (Chp) {
                    __nv_bfloat16 h0 = __float2bfloat16(v0);
                    __nv_bfloat16 h1 = __float2bfloat16(v1);
                    __nv_bfloat16 l0 = __float2bfloat16(v0 - __bfloat162float(h0));
                    __nv_bfloat16 l1 = __float2bfloat16(v1 - __bfloat162float(h1));
                    __nv_bfloat162 hp(h0, h1), lp(l0, l1);
                    *(uint32_t*)(Chp + (long long)gr * Nn + gc) = *(uint32_t*)&hp;
                    *(uint32_t*)(Clp + (long long)gr * Nn + gc) = *(uint32_t*)&lp;
                }
            }
        }
    }
}

// ---------------------------------------------------------------------------
// fp32 -> bf16 hi/lo split
__global__ void __launch_bounds__(256)
split2_bf16(const float4* __restrict__ in, uint2* __restrict__ hi,
            uint2* __restrict__ lo, int n4)
{
    int i = blockIdx.x * blockDim.x + threadIdx.x;
    if (i >= n4) return;
    float4 a = in[i];
    __nv_bfloat16 h0 = __float2bfloat16(a.x), h1 = __float2bfloat16(a.y);
    __nv_bfloat16 h2 = __float2bfloat16(a.z), h3 = __float2bfloat16(a.w);
    __nv_bfloat16 l0 = __float2bfloat16(a.x - __bfloat162float(h0));
    __nv_bfloat16 l1 = __float2bfloat16(a.y - __bfloat162float(h1));
    __nv_bfloat16 l2 = __float2bfloat16(a.z - __bfloat162float(h2));
    __nv_bfloat16 l3 = __float2bfloat16(a.w - __bfloat162float(h3));
    __nv_bfloat162 hA(h0, h1), hB(h2, h3), lA(l0, l1), lB(l2, l3);
    hi[i] = make_uint2(*(uint32_t*)&hA, *(uint32_t*)&hB);
    lo[i] = make_uint2(*(uint32_t*)&lA, *(uint32_t*)&lB);
}

// fp32 -> fp16 (single)
__global__ void __launch_bounds__(256)
split1_f16(const float4* __restrict__ in, uint2* __restrict__ hi, int n4)
{
    int i = blockIdx.x * blockDim.x + threadIdx.x;
    if (i >= n4) return;
    float4 a = in[i];
    __half2 hA(__float2half_rn(a.x), __float2half_rn(a.y));
    __half2 hB(__float2half_rn(a.z), __float2half_rn(a.w));
    hi[i] = make_uint2(*(uint32_t*)&hA, *(uint32_t*)&hB);
}

// ---------------------------------------------------------------------------
// softmax over S axis * v, scattered transposed, emitted as fp16 hi/lo split
__global__ void __launch_bounds__(128)
softmax_mul_scatter(const float* __restrict__ S, const float* __restrict__ V,
                    __half* __restrict__ Yh, __half* __restrict__ Yl)
{
    const int b = blockIdx.y;              // n*H + h  (64)
    const int n = b / HH, h = b % HH;
    const int c = blockIdx.x * 128 + threadIdx.x;

    const float* Sp = S + (long long)b * BSTR;
    const float* Vp = V + (long long)b * BSTR;

    float mx = -INFINITY, sum = 0.f;
    for (int s = 0; s < SS; s++) {
        float v  = Sp[(long long)s * SS + c];
        float m2 = fmaxf(mx, v);
        sum = sum * __expf(mx - m2) + __expf(v - m2);
        mx  = m2;
    }
    const float inv = 1.f / sum;

    __half* Yhp = Yh + (long long)n * SS * DD + (long long)h * HD_ + c;
    __half* Ylp = Yl + (long long)n * SS * DD + (long long)h * HD_ + c;
    for (int s = 0; s < SS; s++) {
        float a = __expf(Sp[(long long)s * SS + c] - mx) * inv;
        float y = a * Vp[(long long)s * SS + c];
        __half hh = __float2half_rn(y);
        __half ll = __float2half_rn(y - __half2float(hh));
        Yhp[(long long)s * DD] = hh;
        Ylp[(long long)s * DD] = ll;
    }
}

// ---------------------------------------------------------------------------
extern "C" void kernel_launch(void* const* d_in, const int* in_sizes, int n_in,
                              void* d_out, int out_size)
{
    const float* query = (const float*)d_in[0];
    const float* key   = (const float*)d_in[1];
    const float* value = (const float*)d_in[2];
    const float* Wq    = (const float*)d_in[3];
    const float* bq    = (const float*)d_in[4];
    const float* Wk    = (const float*)d_in[5];
    const float* bk    = (const float*)d_in[6];
    const float* Wv    = (const float*)d_in[7];
    const float* bv    = (const float*)d_in[8];
    const float* Wo    = (const float*)d_in[9];
    const float* bo    = (const float*)d_in[10];
    float* out = (float*)d_out;

    float *v, *s;
    __nv_bfloat16 *qa_h,*qa_l,*ka_h,*ka_l,*wq_h,*wq_l,*wk_h,*wk_l,*q_h,*q_l,*k_h,*k_l;
    __half *va,*wv,*wo,*y_h,*y_l;
    cudaGetSymbolAddress((void**)&v, g_v);     cudaGetSymbolAddress((void**)&s, g_s);
    cudaGetSymbolAddress((void**)&qa_h, g_qa_h); cudaGetSymbolAddress((void**)&qa_l, g_qa_l);
    cudaGetSymbolAddress((void**)&ka_h, g_ka_h); cudaGetSymbolAddress((void**)&ka_l, g_ka_l);
    cudaGetSymbolAddress((void**)&wq_h, g_wq_h); cudaGetSymbolAddress((void**)&wq_l, g_wq_l);
    cudaGetSymbolAddress((void**)&wk_h, g_wk_h); cudaGetSymbolAddress((void**)&wk_l, g_wk_l);
    cudaGetSymbolAddress((void**)&q_h, g_q_h);   cudaGetSymbolAddress((void**)&q_l, g_q_l);
    cudaGetSymbolAddress((void**)&k_h, g_k_h);   cudaGetSymbolAddress((void**)&k_l, g_k_l);
    cudaGetSymbolAddress((void**)&va, g_va);     cudaGetSymbolAddress((void**)&wv, g_wv);
    cudaGetSymbolAddress((void**)&wo, g_wo);
    cudaGetSymbolAddress((void**)&y_h, g_y_h);   cudaGetSymbolAddress((void**)&y_l, g_y_l);

    // smem sizes per instantiation: stage = 8K*(1+AL) + 16K*(1+BL), stages<=6
    const int SM_330 = 4 * 49152;   // <1,1,0>: 48KB x 4 = 192KB
    const int SM_210 = 6 * 32768;   // <1,0,1>: 32KB x 6 = 192KB
    const int SM_110 = 6 * 24576;   // <0,0,1>: 24KB x 6 = 144KB
    cudaFuncSetAttribute((const void*)gemm_tc<true,true,false>,
                         cudaFuncAttributeMaxDynamicSharedMemorySize, SM_330);
    cudaFuncSetAttribute((const void*)gemm_tc<true,false,true>,
                         cudaFuncAttributeMaxDynamicSharedMemorySize, SM_210);
    cudaFuncSetAttribute((const void*)gemm_tc<false,false,true>,
                         cudaFuncAttributeMaxDynamicSharedMemorySize, SM_110);

    const int n4 = NELT / 4;
    const int sg = (n4 + 255) / 256;
    const dim3 gp(DD / BN, MT / BM, 1);        // 16 x 32, projections
    const dim3 gs(SS / BN, SS / BM, NB * HH);  // 2 x 4 x 64, scores

    // splits
    split2_bf16<<<sg, 256>>>((const float4*)query, (uint2*)qa_h, (uint2*)qa_l, n4);
    split2_bf16<<<sg, 256>>>((const float4*)Wq,    (uint2*)wq_h, (uint2*)wq_l, n4);
    split2_bf16<<<sg, 256>>>((const float4*)key,   (uint2*)ka_h, (uint2*)ka_l, n4);
    split2_bf16<<<sg, 256>>>((const float4*)Wk,    (uint2*)wk_h, (uint2*)wk_l, n4);
    split1_f16 <<<sg, 256>>>((const float4*)value, (uint2*)va, n4);
    split1_f16 <<<sg, 256>>>((const float4*)Wv,    (uint2*)wv, n4);
    split1_f16 <<<sg, 256>>>((const float4*)Wo,    (uint2*)wo, n4);

    // Q projection (bf16 3-pass) -> bf16 split out
    gemm_tc<true,true,false><<<gp, 256, SM_330>>>(
        (const uint16_t*)qa_h, (const uint16_t*)qa_l,
        (const uint16_t*)wq_h, (const uint16_t*)wq_l,
        nullptr, q_h, q_l, bq, DD, DD, 0, 0, 0, 1.f);
    // K projection (bf16 3-pass) -> bf16 split out
    gemm_tc<true,true,false><<<gp, 256, SM_330>>>(
        (const uint16_t*)ka_h, (const uint16_t*)ka_l,
        (const uint16_t*)wk_h, (const uint16_t*)wk_l,
        nullptr, k_h, k_l, bk, DD, DD, 0, 0, 0, 1.f);
    // V projection (fp16 1-pass) -> fp32
    gemm_tc<false,false,true><<<gp, 256, SM_110>>>(
        (const uint16_t*)va, nullptr, (const uint16_t*)wv, nullptr,
        v, nullptr, nullptr, bv, DD, DD, 0, 0, 0, 1.f);
    // Scores (bf16 3-pass), batched, scaled by 1/sqrt(512)
    gemm_tc<true,true,false><<<gs, 256, SM_330>>>(
        (const uint16_t*)q_h, (const uint16_t*)q_l,
        (const uint16_t*)k_h, (const uint16_t*)k_l,
        s, nullptr, nullptr, nullptr, SS, SS, BSTR, BSTR, BSTR,
        0.04419417382415922f);
    // Softmax * v -> transposed fp16 hi/lo
    softmax_mul_scatter<<<dim3(4, NB * HH), 128>>>(s, v, y_h, y_l);
    // Output projection (fp16 2-pass) -> fp32 out
    gemm_tc<true,false,true><<<gp, 256, SM_210>>>(
        (const uint16_t*)y_h, (const uint16_t*)y_l,
        (const uint16_t*)wo, nullptr,
        out, nullptr, nullptr, bo, DD, DD, 0, 0, 0, 1.f);
}

// round 5
// speedup vs baseline: 3.8784x; 1.2021x over previous
#include <cuda_runtime.h>
#include <cuda_bf16.h>
#include <cuda_fp16.h>
#include <math.h>
#include <stdint.h>

// Problem constants
#define NB   8
#define SS   512
#define DD   4096
#define HH   8
#define HD_  512
#define MT   (NB*SS)            // 4096
#define BSTR ((long long)SS*SS) // 262144
#define NELT (MT*DD)            // 16,777,216

// ---------------- scratch (device globals; allocation-guard safe) -----------
__device__ float g_v[NELT];             // V projection (fp32)
__device__ float g_s[NELT];             // scores (fp32)
// bf16 3-pass path (Q/K projections + scores)
__device__ __nv_bfloat16 g_qa_h[NELT], g_qa_l[NELT];
__device__ __nv_bfloat16 g_ka_h[NELT], g_ka_l[NELT];
__device__ __nv_bfloat16 g_wq_h[NELT], g_wq_l[NELT];
__device__ __nv_bfloat16 g_wk_h[NELT], g_wk_l[NELT];
__device__ __nv_bfloat16 g_q_h [NELT], g_q_l [NELT];
__device__ __nv_bfloat16 g_k_h [NELT], g_k_l [NELT];
// fp16 1-pass path (V proj, O proj)
__device__ __half g_va[NELT];
__device__ __half g_wv[NELT];
__device__ __half g_wo[NELT];
__device__ __half g_y_h[NELT];          // Y2 fp16 (hi only)

// ---------------- PTX helpers (compute_103-baseline legal) ------------------
__device__ __forceinline__ uint32_t smem_u32(const void* p) {
    uint32_t a;
    asm("{ .reg .u64 t; cvta.to.shared.u64 t, %1; cvt.u32.u64 %0, t; }"
        : "=r"(a) : "l"(p));
    return a;
}
__device__ __forceinline__ void cp16(uint32_t s, const void* g) {
    asm volatile("cp.async.cg.shared.global [%0], [%1], 16;" :: "r"(s), "l"(g));
}
__device__ __forceinline__ void cp_commit() {
    asm volatile("cp.async.commit_group;");
}
template <int N> __device__ __forceinline__ void cp_wait() {
    asm volatile("cp.async.wait_group %0;" :: "n"(N));
}
__device__ __forceinline__ void ldsm4(uint32_t& r0, uint32_t& r1,
                                      uint32_t& r2, uint32_t& r3, uint32_t a) {
    asm volatile("ldmatrix.sync.aligned.m8n8.x4.shared.b16 {%0,%1,%2,%3}, [%4];"
                 : "=r"(r0), "=r"(r1), "=r"(r2), "=r"(r3) : "r"(a));
}
template<bool FP16>
__device__ __forceinline__ void mma16816(float* d, const uint32_t* a,
                                         uint32_t b0, uint32_t b1) {
    if constexpr (FP16) {
        asm volatile(
            "mma.sync.aligned.m16n8k16.row.col.f32.f16.f16.f32 "
            "{%0,%1,%2,%3}, {%4,%5,%6,%7}, {%8,%9}, {%0,%1,%2,%3};"
            : "+f"(d[0]), "+f"(d[1]), "+f"(d[2]), "+f"(d[3])
            : "r"(a[0]), "r"(a[1]), "r"(a[2]), "r"(a[3]), "r"(b0), "r"(b1));
    } else {
        asm volatile(
            "mma.sync.aligned.m16n8k16.row.col.f32.bf16.bf16.f32 "
            "{%0,%1,%2,%3}, {%4,%5,%6,%7}, {%8,%9}, {%0,%1,%2,%3};"
            : "+f"(d[0]), "+f"(d[1]), "+f"(d[2]), "+f"(d[3])
            : "r"(a[0]), "r"(a[1]), "r"(a[2]), "r"(a[3]), "r"(b0), "r"(b1));
    }
}

// ---------------- tile constants --------------------------------------------
#define BM 128
#define BN 256
#define BK 64
// Unpacked SW128 layout: 128B per row (64 x b16). row r, 16B chunk c:
// byte = r*128 + ((c*16) ^ ((r&7)<<4)).  (validated R3 shape)

// ---------------------------------------------------------------------------
// HMMA NT GEMM: C = scale * A B^T (+ bias).  Passes: AhBh [+ AhBl][+ AlBh].
// A: MxK row-major, B: NxK row-major. blockIdx.z = batch.
// ---------------------------------------------------------------------------
template<bool HAS_AL, bool HAS_BL, bool FP16>
__global__ void __launch_bounds__(256, 1)
gemm_tc(const uint16_t* __restrict__ Ah, const uint16_t* __restrict__ Al,
        const uint16_t* __restrict__ Bh, const uint16_t* __restrict__ Bl,
        float* __restrict__ C, __nv_bfloat16* __restrict__ Ch,
        __nv_bfloat16* __restrict__ Cl, const float* __restrict__ bias,
        int Nn, int Kk, long long sA, long long sB, long long sC, float scale)
{
    constexpr uint32_t SZ_A = 128 * 128;    // 16KB (128 rows x 64k x 2B)
    constexpr uint32_t SZ_B = 256 * 128;    // 32KB (256 rows)
    constexpr uint32_t OFF_AH = 0;
    constexpr uint32_t OFF_BH = SZ_A * (1 + (HAS_AL ? 1 : 0));
    constexpr uint32_t STG_SZ = SZ_A * (1 + (HAS_AL ? 1 : 0))
                              + SZ_B * (1 + (HAS_BL ? 1 : 0));
    constexpr int STAGES = (192u * 1024 / STG_SZ) < 4 ? (int)(192u * 1024 / STG_SZ) : 4;

    extern __shared__ __align__(1024) char smem[];
    const uint32_t sb = smem_u32(smem);
    const int tid = threadIdx.x;
    const int bz = blockIdx.z;
    Ah += (long long)bz * sA;  if (HAS_AL) Al += (long long)bz * sA;
    Bh += (long long)bz * sB;  if (HAS_BL) Bl += (long long)bz * sB;

    const int m0 = blockIdx.y * BM;
    const int n0 = blockIdx.x * BN;
    const int nst = Kk / BK;

    auto load_stage = [&](int s, int buf) {
        const uint32_t stg = sb + (uint32_t)buf * STG_SZ;
        const int kk = s * BK;
        #pragma unroll
        for (int it = 0; it < 4; it++) {          // A: 128 rows x 8 chunks
            int id = tid + it * 256;
            int r = id >> 3, c = id & 7;
            long long go = (long long)(m0 + r) * Kk + kk + c * 8;
            uint32_t so = (uint32_t)(r * 128 + ((c * 16) ^ ((r & 7) << 4)));
            cp16(stg + OFF_AH + so, Ah + go);
            if (HAS_AL) cp16(stg + OFF_AH + SZ_A + so, Al + go);
        }
        #pragma unroll
        for (int it = 0; it < 8; it++) {          // B: 256 rows x 8 chunks
            int id = tid + it * 256;
            int r = id >> 3, c = id & 7;
            long long go = (long long)(n0 + r) * Kk + kk + c * 8;
            uint32_t so = (uint32_t)(r * 128 + ((c * 16) ^ ((r & 7) << 4)));
            cp16(stg + OFF_BH + so, Bh + go);
            if (HAS_BL) cp16(stg + OFF_BH + SZ_B + so, Bl + go);
        }
    };

    // warp layout: 2x4 warps, warp tile 64x64
    const int wid = tid >> 5, lane = tid & 31;
    const int warp_m = wid & 1;
    const int warp_n = wid >> 1;
    const int arow0 = warp_m * 64 + (lane & 15);
    const int brow0 = warp_n * 64 + (lane & 15);
    const uint32_t halfsel = (uint32_t)((lane >> 4) * 16);

    float acc[4][8][4];
    #pragma unroll
    for (int i = 0; i < 4; i++)
        #pragma unroll
        for (int j = 0; j < 8; j++)
            #pragma unroll
            for (int k = 0; k < 4; k++) acc[i][j][k] = 0.f;

    #pragma unroll
    for (int s = 0; s < STAGES - 1; s++) {
        if (s < nst) { load_stage(s, s); cp_commit(); }
    }

    for (int c = 0; c < nst; c++) {
        cp_wait<STAGES - 2>();
        __syncthreads();
        if (c + STAGES - 1 < nst) {
            load_stage(c + STAGES - 1, (c + STAGES - 1) % STAGES);
            cp_commit();
        }
        const uint32_t stg = sb + (uint32_t)(c % STAGES) * STG_SZ;

        #pragma unroll
        for (int ks = 0; ks < 4; ks++) {
            const uint32_t ko = (uint32_t)(ks * 32);
            uint32_t ah[4][4], al[4][4];
            #pragma unroll
            for (int mt = 0; mt < 4; mt++) {
                int row = arow0 + mt * 16;
                uint32_t ad = stg + OFF_AH + (uint32_t)row * 128
                            + ((ko + halfsel) ^ (uint32_t)((row & 7) << 4));
                ldsm4(ah[mt][0], ah[mt][1], ah[mt][2], ah[mt][3], ad);
                if (HAS_AL)
                    ldsm4(al[mt][0], al[mt][1], al[mt][2], al[mt][3], ad + SZ_A);
            }
            #pragma unroll
            for (int g = 0; g < 4; g++) {
                int row = brow0 + g * 16;
                uint32_t bd = stg + OFF_BH + (uint32_t)row * 128
                            + ((ko + halfsel) ^ (uint32_t)((row & 7) << 4));
                uint32_t bh[4], bl[4];
                ldsm4(bh[0], bh[1], bh[2], bh[3], bd);
                if (HAS_BL) ldsm4(bl[0], bl[1], bl[2], bl[3], bd + SZ_B);
                #pragma unroll
                for (int half = 0; half < 2; half++) {
                    const int nt = g * 2 + half;
                    const uint32_t b0h = bh[half], b1h = bh[half + 2];
                    #pragma unroll
                    for (int mt = 0; mt < 4; mt++) {
                        mma16816<FP16>(acc[mt][nt], ah[mt], b0h, b1h);
                        if (HAS_BL)
                            mma16816<FP16>(acc[mt][nt], ah[mt], bl[half], bl[half + 2]);
                        if (HAS_AL)
                            mma16816<FP16>(acc[mt][nt], al[mt], b0h, b1h);
                    }
                }
            }
        }
    }

    // ---- epilogue --------------------------------------------------------
    const int r0 = lane >> 2;
    const int c0 = (lane & 3) * 2;
    float* Cp = C ? (C + (long long)bz * sC) : nullptr;
    __nv_bfloat16* Chp = Ch ? (Ch + (long long)bz * sC) : nullptr;
    __nv_bfloat16* Clp = Cl ? (Cl + (long long)bz * sC) : nullptr;

    #pragma unroll
    for (int mt = 0; mt < 4; mt++) {
        #pragma unroll
        for (int nt = 0; nt < 8; nt++) {
            const int gc = n0 + warp_n * 64 + nt * 8 + c0;
            float b0 = 0.f, b1 = 0.f;
            if (bias) { b0 = __ldg(&bias[gc]); b1 = __ldg(&bias[gc + 1]); }
            #pragma unroll
            for (int hh = 0; hh < 2; hh++) {
                const int gr = m0 + warp_m * 64 + mt * 16 + r0 + hh * 8;
                float v0 = acc[mt][nt][hh * 2 + 0] * scale + b0;
                float v1 = acc[mt][nt][hh * 2 + 1] * scale + b1;
                if (Cp) {
                    float2 o = make_float2(v0, v1);
                    *(float2*)(Cp + (long long)gr * Nn + gc) = o;
                }
                if (Chp) {
                    __nv_bfloat16 h0 = __float2bfloat16(v0);
                    __nv_bfloat16 h1 = __float2bfloat16(v1);
                    __nv_bfloat16 l0 = __float2bfloat16(v0 - __bfloat162float(h0));
                    __nv_bfloat16 l1 = __float2bfloat16(v1 - __bfloat162float(h1));
                    __nv_bfloat162 hp(h0, h1), lp(l0, l1);
                    *(uint32_t*)(Chp + (long long)gr * Nn + gc) = *(uint32_t*)&hp;
                    *(uint32_t*)(Clp + (long long)gr * Nn + gc) = *(uint32_t*)&lp;
                }
            }
        }
    }
}

// ---------------------------------------------------------------------------
// fp32 -> bf16 hi/lo split
__global__ void __launch_bounds__(256)
split2_bf16(const float4* __restrict__ in, uint2* __restrict__ hi,
            uint2* __restrict__ lo, int n4)
{
    int i = blockIdx.x * blockDim.x + threadIdx.x;
    if (i >= n4) return;
    float4 a = in[i];
    __nv_bfloat16 h0 = __float2bfloat16(a.x), h1 = __float2bfloat16(a.y);
    __nv_bfloat16 h2 = __float2bfloat16(a.z), h3 = __float2bfloat16(a.w);
    __nv_bfloat16 l0 = __float2bfloat16(a.x - __bfloat162float(h0));
    __nv_bfloat16 l1 = __float2bfloat16(a.y - __bfloat162float(h1));
    __nv_bfloat16 l2 = __float2bfloat16(a.z - __bfloat162float(h2));
    __nv_bfloat16 l3 = __float2bfloat16(a.w - __bfloat162float(h3));
    __nv_bfloat162 hA(h0, h1), hB(h2, h3), lA(l0, l1), lB(l2, l3);
    hi[i] = make_uint2(*(uint32_t*)&hA, *(uint32_t*)&hB);
    lo[i] = make_uint2(*(uint32_t*)&lA, *(uint32_t*)&lB);
}

// fp32 -> fp16
__global__ void __launch_bounds__(256)
split1_f16(const float4* __restrict__ in, uint2* __restrict__ hi, int n4)
{
    int i = blockIdx.x * blockDim.x + threadIdx.x;
    if (i >= n4) return;
    float4 a = in[i];
    __half2 hA(__float2half_rn(a.x), __float2half_rn(a.y));
    __half2 hB(__float2half_rn(a.z), __float2half_rn(a.w));
    hi[i] = make_uint2(*(uint32_t*)&hA, *(uint32_t*)&hB);
}

// ---------------------------------------------------------------------------
// softmax over S axis * v, scattered transposed, emitted fp16
__global__ void __launch_bounds__(128)
softmax_mul_scatter(const float* __restrict__ S, const float* __restrict__ V,
                    __half* __restrict__ Yh)
{
    const int b = blockIdx.y;              // n*H + h  (64)
    const int n = b / HH, h = b % HH;
    const int c = blockIdx.x * 128 + threadIdx.x;

    const float* Sp = S + (long long)b * BSTR;
    const float* Vp = V + (long long)b * BSTR;

    float mx = -INFINITY, sum = 0.f;
    for (int s = 0; s < SS; s++) {
        float v  = Sp[(long long)s * SS + c];
        float m2 = fmaxf(mx, v);
        sum = sum * __expf(mx - m2) + __expf(v - m2);
        mx  = m2;
    }
    const float inv = 1.f / sum;

    __half* Yhp = Yh + (long long)n * SS * DD + (long long)h * HD_ + c;
    for (int s = 0; s < SS; s++) {
        float a = __expf(Sp[(long long)s * SS + c] - mx) * inv;
        float y = a * Vp[(long long)s * SS + c];
        Yhp[(long long)s * DD] = __float2half_rn(y);
    }
}

// ---------------------------------------------------------------------------
extern "C" void kernel_launch(void* const* d_in, const int* in_sizes, int n_in,
                              void* d_out, int out_size)
{
    const float* query = (const float*)d_in[0];
    const float* key   = (const float*)d_in[1];
    const float* value = (const float*)d_in[2];
    const float* Wq    = (const float*)d_in[3];
    const float* bq    = (const float*)d_in[4];
    const float* Wk    = (const float*)d_in[5];
    const float* bk    = (const float*)d_in[6];
    const float* Wv    = (const float*)d_in[7];
    const float* bv    = (const float*)d_in[8];
    const float* Wo    = (const float*)d_in[9];
    const float* bo    = (const float*)d_in[10];
    float* out = (float*)d_out;

    float *v, *s;
    __nv_bfloat16 *qa_h,*qa_l,*ka_h,*ka_l,*wq_h,*wq_l,*wk_h,*wk_l,*q_h,*q_l,*k_h,*k_l;
    __half *va,*wv,*wo,*y_h;
    cudaGetSymbolAddress((void**)&v, g_v);     cudaGetSymbolAddress((void**)&s, g_s);
    cudaGetSymbolAddress((void**)&qa_h, g_qa_h); cudaGetSymbolAddress((void**)&qa_l, g_qa_l);
    cudaGetSymbolAddress((void**)&ka_h, g_ka_h); cudaGetSymbolAddress((void**)&ka_l, g_ka_l);
    cudaGetSymbolAddress((void**)&wq_h, g_wq_h); cudaGetSymbolAddress((void**)&wq_l, g_wq_l);
    cudaGetSymbolAddress((void**)&wk_h, g_wk_h); cudaGetSymbolAddress((void**)&wk_l, g_wk_l);
    cudaGetSymbolAddress((void**)&q_h, g_q_h);   cudaGetSymbolAddress((void**)&q_l, g_q_l);
    cudaGetSymbolAddress((void**)&k_h, g_k_h);   cudaGetSymbolAddress((void**)&k_l, g_k_l);
    cudaGetSymbolAddress((void**)&va, g_va);     cudaGetSymbolAddress((void**)&wv, g_wv);
    cudaGetSymbolAddress((void**)&wo, g_wo);
    cudaGetSymbolAddress((void**)&y_h, g_y_h);

    // smem: stage = 16K*(1+AL) + 32K*(1+BL); stages = min(192K/stage, 4)
    const int SM_330 = 2 * 98304;   // <1,1,0>: 96KB x 2 = 192KB
    const int SM_110 = 4 * 49152;   // <0,0,1>: 48KB x 4 = 192KB
    cudaFuncSetAttribute((const void*)gemm_tc<true,true,false>,
                         cudaFuncAttributeMaxDynamicSharedMemorySize, SM_330);
    cudaFuncSetAttribute((const void*)gemm_tc<false,false,true>,
                         cudaFuncAttributeMaxDynamicSharedMemorySize, SM_110);

    const int n4 = NELT / 4;
    const int sg = (n4 + 255) / 256;
    const dim3 gp(DD / BN, MT / BM, 1);        // 16 x 32, projections
    const dim3 gs(SS / BN, SS / BM, NB * HH);  // 2 x 4 x 64, scores

    // splits
    split2_bf16<<<sg, 256>>>((const float4*)query, (uint2*)qa_h, (uint2*)qa_l, n4);
    split2_bf16<<<sg, 256>>>((const float4*)Wq,    (uint2*)wq_h, (uint2*)wq_l, n4);
    split2_bf16<<<sg, 256>>>((const float4*)key,   (uint2*)ka_h, (uint2*)ka_l, n4);
    split2_bf16<<<sg, 256>>>((const float4*)Wk,    (uint2*)wk_h, (uint2*)wk_l, n4);
    split1_f16 <<<sg, 256>>>((const float4*)value, (uint2*)va, n4);
    split1_f16 <<<sg, 256>>>((const float4*)Wv,    (uint2*)wv, n4);
    split1_f16 <<<sg, 256>>>((const float4*)Wo,    (uint2*)wo, n4);

    // Q projection (bf16 3-pass) -> bf16 split out
    gemm_tc<true,true,false><<<gp, 256, SM_330>>>(
        (const uint16_t*)qa_h, (const uint16_t*)qa_l,
        (const uint16_t*)wq_h, (const uint16_t*)wq_l,
        nullptr, q_h, q_l, bq, DD, DD, 0, 0, 0, 1.f);
    // K projection (bf16 3-pass) -> bf16 split out
    gemm_tc<true,true,false><<<gp, 256, SM_330>>>(
        (const uint16_t*)ka_h, (const uint16_t*)ka_l,
        (const uint16_t*)wk_h, (const uint16_t*)wk_l,
        nullptr, k_h, k_l, bk, DD, DD, 0, 0, 0, 1.f);
    // V projection (fp16 1-pass) -> fp32
    gemm_tc<false,false,true><<<gp, 256, SM_110>>>(
        (const uint16_t*)va, nullptr, (const uint16_t*)wv, nullptr,
        v, nullptr, nullptr, bv, DD, DD, 0, 0, 0, 1.f);
    // Scores (bf16 3-pass), batched, scaled by 1/sqrt(512)
    gemm_tc<true,true,false><<<gs, 256, SM_330>>>(
        (const uint16_t*)q_h, (const uint16_t*)q_l,
        (const uint16_t*)k_h, (const uint16_t*)k_l,
        s, nullptr, nullptr, nullptr, SS, SS, BSTR, BSTR, BSTR,
        0.04419417382415922f);
    // Softmax * v -> transposed fp16 (hi only)
    softmax_mul_scatter<<<dim3(4, NB * HH), 128>>>(s, v, y_h);
    // Output projection (fp16 1-pass) -> fp32 out
    gemm_tc<false,false,true><<<gp, 256, SM_110>>>(
        (const uint16_t*)y_h, nullptr, (const uint16_t*)wo, nullptr,
        out, nullptr, nullptr, bo, DD, DD, 0, 0, 0, 1.f);
}

// round 6
// speedup vs baseline: 4.1206x; 1.0624x over previous
#include <cuda_runtime.h>
#include <cuda_bf16.h>
#include <cuda_fp16.h>
#include <math.h>
#include <stdint.h>

// Problem constants
#define NB   8
#define SS   512
#define DD   4096
#define HH   8
#define HD_  512
#define MT   (NB*SS)            // 4096
#define BSTR ((long long)SS*SS) // 262144
#define NELT (MT*DD)            // 16,777,216

// ---------------- scratch (device globals; allocation-guard safe) -----------
__device__ float g_v[NELT];             // V projection (fp32)
__device__ float g_s[NELT];             // scores (fp32)
__device__ __nv_bfloat16 g_qa_h[NELT], g_qa_l[NELT];
__device__ __nv_bfloat16 g_ka_h[NELT], g_ka_l[NELT];
__device__ __nv_bfloat16 g_wq_h[NELT], g_wq_l[NELT];
__device__ __nv_bfloat16 g_wk_h[NELT], g_wk_l[NELT];
__device__ __nv_bfloat16 g_q_h [NELT], g_q_l [NELT];
__device__ __nv_bfloat16 g_k_h [NELT], g_k_l [NELT];
__device__ __half g_va[NELT];
__device__ __half g_wv[NELT];
__device__ __half g_wo[NELT];
__device__ __half g_y_h[NELT];          // Y2 fp16 (hi only)

// ---------------- PTX helpers (compute_103-baseline legal) ------------------
__device__ __forceinline__ uint32_t smem_u32(const void* p) {
    uint32_t a;
    asm("{ .reg .u64 t; cvta.to.shared.u64 t, %1; cvt.u32.u64 %0, t; }"
        : "=r"(a) : "l"(p));
    return a;
}
__device__ __forceinline__ void cp16(uint32_t s, const void* g) {
    asm volatile("cp.async.cg.shared.global [%0], [%1], 16;" :: "r"(s), "l"(g));
}
__device__ __forceinline__ void cp_commit() {
    asm volatile("cp.async.commit_group;");
}
template <int N> __device__ __forceinline__ void cp_wait() {
    asm volatile("cp.async.wait_group %0;" :: "n"(N));
}
__device__ __forceinline__ void ldsm4(uint32_t& r0, uint32_t& r1,
                                      uint32_t& r2, uint32_t& r3, uint32_t a) {
    asm volatile("ldmatrix.sync.aligned.m8n8.x4.shared.b16 {%0,%1,%2,%3}, [%4];"
                 : "=r"(r0), "=r"(r1), "=r"(r2), "=r"(r3) : "r"(a));
}
template<bool FP16>
__device__ __forceinline__ void mma16816(float* d, const uint32_t* a,
                                         uint32_t b0, uint32_t b1) {
    if constexpr (FP16) {
        asm volatile(
            "mma.sync.aligned.m16n8k16.row.col.f32.f16.f16.f32 "
            "{%0,%1,%2,%3}, {%4,%5,%6,%7}, {%8,%9}, {%0,%1,%2,%3};"
            : "+f"(d[0]), "+f"(d[1]), "+f"(d[2]), "+f"(d[3])
            : "r"(a[0]), "r"(a[1]), "r"(a[2]), "r"(a[3]), "r"(b0), "r"(b1));
    } else {
        asm volatile(
            "mma.sync.aligned.m16n8k16.row.col.f32.bf16.bf16.f32 "
            "{%0,%1,%2,%3}, {%4,%5,%6,%7}, {%8,%9}, {%0,%1,%2,%3};"
            : "+f"(d[0]), "+f"(d[1]), "+f"(d[2]), "+f"(d[3])
            : "r"(a[0]), "r"(a[1]), "r"(a[2]), "r"(a[3]), "r"(b0), "r"(b1));
    }
}

// ---------------- tile constants --------------------------------------------
#define BM 128
#define BN 128
#define BK 64
// SW128 layout: 128B per row (64 x b16). row r, 16B chunk c:
// byte = r*128 + ((c*16) ^ ((r&7)<<4)).

// ---------------------------------------------------------------------------
// HMMA NT GEMM: C = scale * A B^T (+ bias).  Passes: AhBh [+ AhBl][+ AlBh].
// A: MxK row-major, B: NxK row-major. blockIdx.z = batch.
// 8 warps (2x4), warp tile 64x32. MINB = min blocks/SM (2 for 1-pass fp16).
// ---------------------------------------------------------------------------
template<bool HAS_AL, bool HAS_BL, bool FP16, int MINB>
__global__ void __launch_bounds__(256, MINB)
gemm_tc(const uint16_t* __restrict__ Ah, const uint16_t* __restrict__ Al,
        const uint16_t* __restrict__ Bh, const uint16_t* __restrict__ Bl,
        float* __restrict__ C, __nv_bfloat16* __restrict__ Ch,
        __nv_bfloat16* __restrict__ Cl, const float* __restrict__ bias,
        int Nn, int Kk, long long sA, long long sB, long long sC, float scale)
{
    constexpr uint32_t SZ_A = 128 * 128;    // 16KB
    constexpr uint32_t SZ_B = 128 * 128;    // 16KB
    constexpr uint32_t OFF_BH = SZ_A * (1 + (HAS_AL ? 1 : 0));
    constexpr uint32_t STG_SZ = SZ_A * (1 + (HAS_AL ? 1 : 0))
                              + SZ_B * (1 + (HAS_BL ? 1 : 0));
    constexpr int STAGES = 3;               // 3-pass: 192KB; 1-pass: 96KB x2CTA

    extern __shared__ __align__(1024) char smem[];
    const uint32_t sb = smem_u32(smem);
    const int tid = threadIdx.x;
    const int bz = blockIdx.z;
    Ah += (long long)bz * sA;  if (HAS_AL) Al += (long long)bz * sA;
    Bh += (long long)bz * sB;  if (HAS_BL) Bl += (long long)bz * sB;

    const int m0 = blockIdx.y * BM;
    const int n0 = blockIdx.x * BN;
    const int nst = Kk / BK;

    auto load_stage = [&](int s, int buf) {
        const uint32_t stg = sb + (uint32_t)buf * STG_SZ;
        const int kk = s * BK;
        #pragma unroll
        for (int it = 0; it < 4; it++) {          // A: 128 rows x 8 chunks
            int id = tid + it * 256;
            int r = id >> 3, c = id & 7;
            long long go = (long long)(m0 + r) * Kk + kk + c * 8;
            uint32_t so = (uint32_t)(r * 128 + ((c * 16) ^ ((r & 7) << 4)));
            cp16(stg + so, Ah + go);
            if (HAS_AL) cp16(stg + SZ_A + so, Al + go);
        }
        #pragma unroll
        for (int it = 0; it < 4; it++) {          // B: 128 rows x 8 chunks
            int id = tid + it * 256;
            int r = id >> 3, c = id & 7;
            long long go = (long long)(n0 + r) * Kk + kk + c * 8;
            uint32_t so = (uint32_t)(r * 128 + ((c * 16) ^ ((r & 7) << 4)));
            cp16(stg + OFF_BH + so, Bh + go);
            if (HAS_BL) cp16(stg + OFF_BH + SZ_B + so, Bl + go);
        }
    };

    // warp layout: 2x4 warps, warp tile 64x32
    const int wid = tid >> 5, lane = tid & 31;
    const int warp_m = wid & 1;        // 0..1 -> 64 rows each
    const int warp_n = wid >> 1;       // 0..3 -> 32 cols each
    const int arow0 = warp_m * 64 + (lane & 15);
    const int brow0 = warp_n * 32 + (lane & 15);
    const uint32_t halfsel = (uint32_t)((lane >> 4) * 16);

    float acc[4][4][4];
    #pragma unroll
    for (int i = 0; i < 4; i++)
        #pragma unroll
        for (int j = 0; j < 4; j++)
            #pragma unroll
            for (int k = 0; k < 4; k++) acc[i][j][k] = 0.f;

    #pragma unroll
    for (int s = 0; s < STAGES - 1; s++) {
        if (s < nst) { load_stage(s, s); cp_commit(); }
    }

    for (int c = 0; c < nst; c++) {
        cp_wait<STAGES - 2>();
        __syncthreads();
        if (c + STAGES - 1 < nst) {
            load_stage(c + STAGES - 1, (c + STAGES - 1) % STAGES);
            cp_commit();
        }
        const uint32_t stg = sb + (uint32_t)(c % STAGES) * STG_SZ;

        #pragma unroll
        for (int ks = 0; ks < 4; ks++) {
            const uint32_t ko = (uint32_t)(ks * 32);
            uint32_t ah[4][4], al[4][4];
            #pragma unroll
            for (int mt = 0; mt < 4; mt++) {
                int row = arow0 + mt * 16;
                uint32_t ad = stg + (uint32_t)row * 128
                            + ((ko + halfsel) ^ (uint32_t)((row & 7) << 4));
                ldsm4(ah[mt][0], ah[mt][1], ah[mt][2], ah[mt][3], ad);
                if (HAS_AL)
                    ldsm4(al[mt][0], al[mt][1], al[mt][2], al[mt][3], ad + SZ_A);
            }
            #pragma unroll
            for (int g = 0; g < 2; g++) {
                int row = brow0 + g * 16;
                uint32_t bd = stg + OFF_BH + (uint32_t)row * 128
                            + ((ko + halfsel) ^ (uint32_t)((row & 7) << 4));
                uint32_t bh[4], bl[4];
                ldsm4(bh[0], bh[1], bh[2], bh[3], bd);
                if (HAS_BL) ldsm4(bl[0], bl[1], bl[2], bl[3], bd + SZ_B);
                #pragma unroll
                for (int half = 0; half < 2; half++) {
                    const int nt = g * 2 + half;
                    const uint32_t b0h = bh[half], b1h = bh[half + 2];
                    #pragma unroll
                    for (int mt = 0; mt < 4; mt++) {
                        mma16816<FP16>(acc[mt][nt], ah[mt], b0h, b1h);
                        if (HAS_BL)
                            mma16816<FP16>(acc[mt][nt], ah[mt], bl[half], bl[half + 2]);
                        if (HAS_AL)
                            mma16816<FP16>(acc[mt][nt], al[mt], b0h, b1h);
                    }
                }
            }
        }
    }

    // ---- epilogue --------------------------------------------------------
    const int r0 = lane >> 2;
    const int c0 = (lane & 3) * 2;
    float* Cp = C ? (C + (long long)bz * sC) : nullptr;
    __nv_bfloat16* Chp = Ch ? (Ch + (long long)bz * sC) : nullptr;
    __nv_bfloat16* Clp = Cl ? (Cl + (long long)bz * sC) : nullptr;

    #pragma unroll
    for (int mt = 0; mt < 4; mt++) {
        #pragma unroll
        for (int nt = 0; nt < 4; nt++) {
            const int gc = n0 + warp_n * 32 + nt * 8 + c0;
            float b0 = 0.f, b1 = 0.f;
            if (bias) { b0 = __ldg(&bias[gc]); b1 = __ldg(&bias[gc + 1]); }
            #pragma unroll
            for (int hh = 0; hh < 2; hh++) {
                const int gr = m0 + warp_m * 64 + mt * 16 + r0 + hh * 8;
                float v0 = acc[mt][nt][hh * 2 + 0] * scale + b0;
                float v1 = acc[mt][nt][hh * 2 + 1] * scale + b1;
                if (Cp) {
                    float2 o = make_float2(v0, v1);
                    *(float2*)(Cp + (long long)gr * Nn + gc) = o;
                }
                if (Chp) {
                    __nv_bfloat16 h0 = __float2bfloat16(v0);
                    __nv_bfloat16 h1 = __float2bfloat16(v1);
                    __nv_bfloat16 l0 = __float2bfloat16(v0 - __bfloat162float(h0));
                    __nv_bfloat16 l1 = __float2bfloat16(v1 - __bfloat162float(h1));
                    __nv_bfloat162 hp(h0, h1), lp(l0, l1);
                    *(uint32_t*)(Chp + (long long)gr * Nn + gc) = *(uint32_t*)&hp;
                    *(uint32_t*)(Clp + (long long)gr * Nn + gc) = *(uint32_t*)&lp;
                }
            }
        }
    }
}

// ---------------------------------------------------------------------------
// fp32 -> bf16 hi/lo split
__global__ void __launch_bounds__(256)
split2_bf16(const float4* __restrict__ in, uint2* __restrict__ hi,
            uint2* __restrict__ lo, int n4)
{
    int i = blockIdx.x * blockDim.x + threadIdx.x;
    if (i >= n4) return;
    float4 a = in[i];
    __nv_bfloat16 h0 = __float2bfloat16(a.x), h1 = __float2bfloat16(a.y);
    __nv_bfloat16 h2 = __float2bfloat16(a.z), h3 = __float2bfloat16(a.w);
    __nv_bfloat16 l0 = __float2bfloat16(a.x - __bfloat162float(h0));
    __nv_bfloat16 l1 = __float2bfloat16(a.y - __bfloat162float(h1));
    __nv_bfloat16 l2 = __float2bfloat16(a.z - __bfloat162float(h2));
    __nv_bfloat16 l3 = __float2bfloat16(a.w - __bfloat162float(h3));
    __nv_bfloat162 hA(h0, h1), hB(h2, h3), lA(l0, l1), lB(l2, l3);
    hi[i] = make_uint2(*(uint32_t*)&hA, *(uint32_t*)&hB);
    lo[i] = make_uint2(*(uint32_t*)&lA, *(uint32_t*)&lB);
}

// fp32 -> fp16
__global__ void __launch_bounds__(256)
split1_f16(const float4* __restrict__ in, uint2* __restrict__ hi, int n4)
{
    int i = blockIdx.x * blockDim.x + threadIdx.x;
    if (i >= n4) return;
    float4 a = in[i];
    __half2 hA(__float2half_rn(a.x), __float2half_rn(a.y));
    __half2 hB(__float2half_rn(a.z), __float2half_rn(a.w));
    hi[i] = make_uint2(*(uint32_t*)&hA, *(uint32_t*)&hB);
}

// ---------------------------------------------------------------------------
// softmax over S axis * v, scattered transposed, emitted fp16
__global__ void __launch_bounds__(128)
softmax_mul_scatter(const float* __restrict__ S, const float* __restrict__ V,
                    __half* __restrict__ Yh)
{
    const int b = blockIdx.y;              // n*H + h  (64)
    const int n = b / HH, h = b % HH;
    const int c = blockIdx.x * 128 + threadIdx.x;

    const float* Sp = S + (long long)b * BSTR;
    const float* Vp = V + (long long)b * BSTR;

    float mx = -INFINITY, sum = 0.f;
    for (int s = 0; s < SS; s++) {
        float v  = Sp[(long long)s * SS + c];
        float m2 = fmaxf(mx, v);
        sum = sum * __expf(mx - m2) + __expf(v - m2);
        mx  = m2;
    }
    const float inv = 1.f / sum;

    __half* Yhp = Yh + (long long)n * SS * DD + (long long)h * HD_ + c;
    for (int s = 0; s < SS; s++) {
        float a = __expf(Sp[(long long)s * SS + c] - mx) * inv;
        float y = a * Vp[(long long)s * SS + c];
        Yhp[(long long)s * DD] = __float2half_rn(y);
    }
}

// ---------------------------------------------------------------------------
extern "C" void kernel_launch(void* const* d_in, const int* in_sizes, int n_in,
                              void* d_out, int out_size)
{
    const float* query = (const float*)d_in[0];
    const float* key   = (const float*)d_in[1];
    const float* value = (const float*)d_in[2];
    const float* Wq    = (const float*)d_in[3];
    const float* bq    = (const float*)d_in[4];
    const float* Wk    = (const float*)d_in[5];
    const float* bk    = (const float*)d_in[6];
    const float* Wv    = (const float*)d_in[7];
    const float* bv    = (const float*)d_in[8];
    const float* Wo    = (const float*)d_in[9];
    const float* bo    = (const float*)d_in[10];
    float* out = (float*)d_out;

    float *v, *s;
    __nv_bfloat16 *qa_h,*qa_l,*ka_h,*ka_l,*wq_h,*wq_l,*wk_h,*wk_l,*q_h,*q_l,*k_h,*k_l;
    __half *va,*wv,*wo,*y_h;
    cudaGetSymbolAddress((void**)&v, g_v);     cudaGetSymbolAddress((void**)&s, g_s);
    cudaGetSymbolAddress((void**)&qa_h, g_qa_h); cudaGetSymbolAddress((void**)&qa_l, g_qa_l);
    cudaGetSymbolAddress((void**)&ka_h, g_ka_h); cudaGetSymbolAddress((void**)&ka_l, g_ka_l);
    cudaGetSymbolAddress((void**)&wq_h, g_wq_h); cudaGetSymbolAddress((void**)&wq_l, g_wq_l);
    cudaGetSymbolAddress((void**)&wk_h, g_wk_h); cudaGetSymbolAddress((void**)&wk_l, g_wk_l);
    cudaGetSymbolAddress((void**)&q_h, g_q_h);   cudaGetSymbolAddress((void**)&q_l, g_q_l);
    cudaGetSymbolAddress((void**)&k_h, g_k_h);   cudaGetSymbolAddress((void**)&k_l, g_k_l);
    cudaGetSymbolAddress((void**)&va, g_va);     cudaGetSymbolAddress((void**)&wv, g_wv);
    cudaGetSymbolAddress((void**)&wo, g_wo);
    cudaGetSymbolAddress((void**)&y_h, g_y_h);

    // smem: 3-pass stage 64KB x3 = 192KB (1 CTA); 1-pass stage 32KB x3 = 96KB (2 CTA)
    const int SM_330 = 3 * 65536;
    const int SM_110 = 3 * 32768;
    cudaFuncSetAttribute((const void*)gemm_tc<true,true,false,1>,
                         cudaFuncAttributeMaxDynamicSharedMemorySize, SM_330);
    cudaFuncSetAttribute((const void*)gemm_tc<false,false,true,2>,
                         cudaFuncAttributeMaxDynamicSharedMemorySize, SM_110);

    const int n4 = NELT / 4;
    const int sg = (n4 + 255) / 256;
    const dim3 gp(DD / BN, MT / BM, 1);        // 32 x 32, projections
    const dim3 gs(SS / BN, SS / BM, NB * HH);  // 4 x 4 x 64, scores

    // splits
    split2_bf16<<<sg, 256>>>((const float4*)query, (uint2*)qa_h, (uint2*)qa_l, n4);
    split2_bf16<<<sg, 256>>>((const float4*)Wq,    (uint2*)wq_h, (uint2*)wq_l, n4);
    split2_bf16<<<sg, 256>>>((const float4*)key,   (uint2*)ka_h, (uint2*)ka_l, n4);
    split2_bf16<<<sg, 256>>>((const float4*)Wk,    (uint2*)wk_h, (uint2*)wk_l, n4);
    split1_f16 <<<sg, 256>>>((const float4*)value, (uint2*)va, n4);
    split1_f16 <<<sg, 256>>>((const float4*)Wv,    (uint2*)wv, n4);
    split1_f16 <<<sg, 256>>>((const float4*)Wo,    (uint2*)wo, n4);

    // Q projection (bf16 3-pass) -> bf16 split out
    gemm_tc<true,true,false,1><<<gp, 256, SM_330>>>(
        (const uint16_t*)qa_h, (const uint16_t*)qa_l,
        (const uint16_t*)wq_h, (const uint16_t*)wq_l,
        nullptr, q_h, q_l, bq, DD, DD, 0, 0, 0, 1.f);
    // K projection (bf16 3-pass) -> bf16 split out
    gemm_tc<true,true,false,1><<<gp, 256, SM_330>>>(
        (const uint16_t*)ka_h, (const uint16_t*)ka_l,
        (const uint16_t*)wk_h, (const uint16_t*)wk_l,
        nullptr, k_h, k_l, bk, DD, DD, 0, 0, 0, 1.f);
    // V projection (fp16 1-pass) -> fp32
    gemm_tc<false,false,true,2><<<gp, 256, SM_110>>>(
        (const uint16_t*)va, nullptr, (const uint16_t*)wv, nullptr,
        v, nullptr, nullptr, bv, DD, DD, 0, 0, 0, 1.f);
    // Scores (bf16 3-pass), batched, scaled by 1/sqrt(512)
    gemm_tc<true,true,false,1><<<gs, 256, SM_330>>>(
        (const uint16_t*)q_h, (const uint16_t*)q_l,
        (const uint16_t*)k_h, (const uint16_t*)k_l,
        s, nullptr, nullptr, nullptr, SS, SS, BSTR, BSTR, BSTR,
        0.04419417382415922f);
    // Softmax * v -> transposed fp16 (hi only)
    softmax_mul_scatter<<<dim3(4, NB * HH), 128>>>(s, v, y_h);
    // Output projection (fp16 1-pass) -> fp32 out
    gemm_tc<false,false,true,2><<<gp, 256, SM_110>>>(
        (const uint16_t*)y_h, nullptr, (const uint16_t*)wo, nullptr,
        out, nullptr, nullptr, bo, DD, DD, 0, 0, 0, 1.f);
}